// round 2
// baseline (speedup 1.0000x reference)
#include <cuda_runtime.h>
#include <math.h>

// Problem constants (fixed by setup_inputs)
#define Bsz 2
#define Sq  2048
#define Dm  1024
#define Hn  8
#define NEGV (-1e10f)

// Scratch (device globals; no allocations allowed)
__device__ float g_q[Bsz * Sq * Dm];        // 16 MB  q = x @ wi
__device__ float g_scores[Bsz * Sq * Sq];   // 32 MB  attention scores / probs
__device__ float g_head[Bsz * Sq * Dm];     // 16 MB  head = q + P@q ; later reused for ffn act
__device__ float g_h[Bsz * Sq * Dm];        // 16 MB  h = head @ Weff (+ln in place)
__device__ float g_weff[Dm * Dm];           // 4 MB   folded out_kernel

// ---------------------------------------------------------------------------
// Fold out_kernel [H*D, D] -> Weff[D, D] = sum over heads
// ---------------------------------------------------------------------------
__global__ void fold_wout(const float* __restrict__ ok, float* __restrict__ w) {
    int i = blockIdx.x * 256 + threadIdx.x;   // 0 .. D*D-1
    float s = 0.f;
#pragma unroll
    for (int h = 0; h < Hn; h++) s += ok[(size_t)h * Dm * Dm + i];
    w[i] = s;
}

// ---------------------------------------------------------------------------
// Generic tiled SGEMM: C[M,N] = epilogue(A[M,K] @ B)
//   BT=false: B is [K,N] row-major (NN). BT=true: B is [N,K] row-major (NT).
//   CK=true:  K-loop truncated at (blockRow+1)*BM  (causal PV gemm)
//   EPI: 0 plain | 1 scale+causal mask (scores) | 2 +residual | 3 +bias | 4 swish
//   blockIdx.z = batch; sA/sB/sC/sR are per-batch element strides (0 = shared).
// ---------------------------------------------------------------------------
#define BMm 128
#define BNn 128
#define BKk 16

template <int EPI, bool BT, bool CK>
__global__ __launch_bounds__(256)
void sgemm(const float* __restrict__ A, const float* __restrict__ B,
           float* __restrict__ C, int M, int N, int K,
           long sA, long sB, long sC,
           float alpha, const float* __restrict__ bias,
           const float* __restrict__ resid, long sR)
{
    if (EPI == 1 && blockIdx.x > blockIdx.y) return;   // upper-tri score blocks untouched

    const int bz = blockIdx.z;
    A += (size_t)bz * sA;
    B += (size_t)bz * sB;
    C += (size_t)bz * sC;

    const int m0 = blockIdx.y * BMm;
    const int n0 = blockIdx.x * BNn;
    int Keff = K;
    if (CK) Keff = min(K, (int)(blockIdx.y + 1) * BMm);

    __shared__ float As[BKk][BMm];
    __shared__ float Bs[BKk][BNn];

    const int t  = threadIdx.x;     // 0..255
    const int tx = t & 15;
    const int ty = t >> 4;

    // A (and transposed-B) tile loader indices: 128 rows x 16 cols
    const int aRow = t >> 2;          // 0..63
    const int aCol = (t & 3) << 2;    // 0,4,8,12
    // NN B tile loader indices: 16 rows x 128 cols
    const int bRow = t >> 5;          // 0..7
    const int bCol = (t & 31) << 2;   // 0..124

    float acc[8][8];
#pragma unroll
    for (int i = 0; i < 8; i++)
#pragma unroll
        for (int j = 0; j < 8; j++) acc[i][j] = 0.f;

    for (int k0 = 0; k0 < Keff; k0 += BKk) {
#pragma unroll
        for (int r = 0; r < 2; r++) {
            float4 v = *(const float4*)&A[(size_t)(m0 + aRow + r * 64) * K + k0 + aCol];
            As[aCol + 0][aRow + r * 64] = v.x;
            As[aCol + 1][aRow + r * 64] = v.y;
            As[aCol + 2][aRow + r * 64] = v.z;
            As[aCol + 3][aRow + r * 64] = v.w;
        }
        if (BT) {
#pragma unroll
            for (int r = 0; r < 2; r++) {
                float4 v = *(const float4*)&B[(size_t)(n0 + aRow + r * 64) * K + k0 + aCol];
                Bs[aCol + 0][aRow + r * 64] = v.x;
                Bs[aCol + 1][aRow + r * 64] = v.y;
                Bs[aCol + 2][aRow + r * 64] = v.z;
                Bs[aCol + 3][aRow + r * 64] = v.w;
            }
        } else {
#pragma unroll
            for (int r = 0; r < 2; r++) {
                float4 v = *(const float4*)&B[(size_t)(k0 + bRow + r * 8) * N + n0 + bCol];
                *(float4*)&Bs[bRow + r * 8][bCol] = v;
            }
        }
        __syncthreads();

#pragma unroll
        for (int k = 0; k < BKk; k++) {
            float a[8], b[8];
            *(float4*)&a[0] = *(const float4*)&As[k][ty * 8];
            *(float4*)&a[4] = *(const float4*)&As[k][ty * 8 + 4];
            *(float4*)&b[0] = *(const float4*)&Bs[k][tx * 8];
            *(float4*)&b[4] = *(const float4*)&Bs[k][tx * 8 + 4];
#pragma unroll
            for (int i = 0; i < 8; i++)
#pragma unroll
                for (int j = 0; j < 8; j++) acc[i][j] += a[i] * b[j];
        }
        __syncthreads();
    }

#pragma unroll
    for (int i = 0; i < 8; i++) {
        const int row = m0 + ty * 8 + i;
        float* crow = C + (size_t)row * N + n0 + tx * 8;
        float vals[8];
#pragma unroll
        for (int j = 0; j < 8; j++) {
            float v = acc[i][j];
            const int col = n0 + tx * 8 + j;
            if (EPI == 1) v = (col <= row) ? v * alpha : NEGV;
            if (EPI == 2) v += resid[(size_t)bz * sR + (size_t)row * N + col];
            if (EPI == 3) v += bias[col];
            if (EPI == 4) v = v / (1.f + __expf(-v));
            vals[j] = v;
        }
        *(float4*)&crow[0] = *(float4*)&vals[0];
        *(float4*)&crow[4] = *(float4*)&vals[4];
    }
}

// ---------------------------------------------------------------------------
// Row softmax over causal prefix. Row i valid length L = roundup(i+1, 128).
// Masked tail inside the diagonal 128-block holds NEGV -> exp underflows to 0.
// ---------------------------------------------------------------------------
__global__ void softmax_rows(float* __restrict__ sc) {
    const int rowg = blockIdx.x;              // 0 .. Bsz*Sq-1
    const int b = rowg / Sq, r = rowg % Sq;
    float* p = sc + (size_t)b * Sq * Sq + (size_t)r * Sq;
    const int L = ((r >> 7) + 1) << 7;        // multiple of 128, <= 2048
    const int t = threadIdx.x;                // 256 threads

    float vals[8];
    int cnt = 0;
    float mx = -INFINITY;
    for (int j = t; j < L; j += 256) { float v = p[j]; vals[cnt++] = v; mx = fmaxf(mx, v); }

    __shared__ float red[256];
    red[t] = mx; __syncthreads();
    for (int s = 128; s > 0; s >>= 1) { if (t < s) red[t] = fmaxf(red[t], red[t + s]); __syncthreads(); }
    mx = red[0]; __syncthreads();

    float sum = 0.f;
    for (int i = 0; i < cnt; i++) { vals[i] = __expf(vals[i] - mx); sum += vals[i]; }
    red[t] = sum; __syncthreads();
    for (int s = 128; s > 0; s >>= 1) { if (t < s) red[t] += red[t + s]; __syncthreads(); }
    const float inv = 1.f / red[0];

    cnt = 0;
    for (int j = t; j < L; j += 256) p[j] = vals[cnt++] * inv;
}

// ---------------------------------------------------------------------------
// LayerNorm (no scale/bias), E[x^2]-E[x]^2 variance, eps=1e-5. Row length 1024.
// ---------------------------------------------------------------------------
__global__ void layernorm_rows(float* __restrict__ h) {
    const int row = blockIdx.x;
    float* p = h + (size_t)row * Dm;
    const int t = threadIdx.x;  // 256 threads, 4 elems each
    float4 v = *(float4*)&p[t * 4];
    float s  = v.x + v.y + v.z + v.w;
    float sq = v.x * v.x + v.y * v.y + v.z * v.z + v.w * v.w;

    __shared__ float rs[256], rq[256];
    rs[t] = s; rq[t] = sq; __syncthreads();
    for (int k = 128; k > 0; k >>= 1) {
        if (t < k) { rs[t] += rs[t + k]; rq[t] += rq[t + k]; }
        __syncthreads();
    }
    const float mean = rs[0] * (1.f / Dm);
    const float var  = rq[0] * (1.f / Dm) - mean * mean;
    const float inv  = rsqrtf(var + 1e-5f);
    v.x = (v.x - mean) * inv;
    v.y = (v.y - mean) * inv;
    v.z = (v.z - mean) * inv;
    v.w = (v.w - mean) * inv;
    *(float4*)&p[t * 4] = v;
}

// ---------------------------------------------------------------------------
extern "C" void kernel_launch(void* const* d_in, const int* in_sizes, int n_in,
                              void* d_out, int out_size)
{
    const float* x  = (const float*)d_in[0];   // [B,S,D]
    // d_in[1] = mask (causal tril, structure hardcoded)
    const float* wi = (const float*)d_in[2];   // [D,D]
    const float* ok = (const float*)d_in[3];   // [H*D,D]
    const float* ob = (const float*)d_in[4];   // [D]
    float* out = (float*)d_out;                // [B,S,D]

    float *q, *sc, *head, *h, *weff;
    cudaGetSymbolAddress((void**)&q,    g_q);
    cudaGetSymbolAddress((void**)&sc,   g_scores);
    cudaGetSymbolAddress((void**)&head, g_head);
    cudaGetSymbolAddress((void**)&h,    g_h);
    cudaGetSymbolAddress((void**)&weff, g_weff);

    const int MS = Bsz * Sq;          // 4096
    const long sQ  = (long)Sq * Dm;   // per-batch stride of q/head/h
    const long sSS = (long)Sq * Sq;   // per-batch stride of scores

    // 1. fold out_kernel
    fold_wout<<<(Dm * Dm) / 256, 256>>>(ok, weff);

    // 2. q = x @ wi                         [4096,1024] = [4096,1024]@[1024,1024]
    sgemm<0, false, false><<<dim3(Dm / BNn, MS / BMm, 1), 256>>>(
        x, wi, q, MS, Dm, Dm, 0, 0, 0, 0.f, nullptr, nullptr, 0);

    // 3. scores = (q @ q^T) / 32, causal-masked; lower-tri blocks only
    sgemm<1, true, false><<<dim3(Sq / BNn, Sq / BMm, Bsz), 256>>>(
        q, q, sc, Sq, Sq, Dm, sQ, sQ, sSS, 1.f / 32.f, nullptr, nullptr, 0);

    // 4. softmax rows (causal prefix)
    softmax_rows<<<Bsz * Sq, 256>>>(sc);

    // 5. head = P @ q + q  (K truncated causally per block-row)
    sgemm<2, false, true><<<dim3(Dm / BNn, Sq / BMm, Bsz), 256>>>(
        sc, q, head, Sq, Dm, Sq, sSS, sQ, sQ, 0.f, nullptr, q, sQ);

    // 6. h = head @ Weff + out_bias
    sgemm<3, false, false><<<dim3(Dm / BNn, MS / BMm, 1), 256>>>(
        head, weff, h, MS, Dm, Dm, 0, 0, 0, 0.f, ob, nullptr, 0);

    // 7. layernorm in place
    layernorm_rows<<<Bsz * Sq, 256>>>(h);

    // 8. act = swish(h @ wi)   (reuse g_head)
    sgemm<4, false, false><<<dim3(Dm / BNn, MS / BMm, 1), 256>>>(
        h, wi, head, MS, Dm, Dm, 0, 0, 0, 0.f, nullptr, nullptr, 0);

    // 9. out = act @ wi
    sgemm<0, false, false><<<dim3(Dm / BNn, MS / BMm, 1), 256>>>(
        head, wi, out, MS, Dm, Dm, 0, 0, 0, 0.f, nullptr, nullptr, 0);
}

// round 3
// speedup vs baseline: 2.6017x; 2.6017x over previous
#include <cuda_runtime.h>
#include <math.h>
#include <stdint.h>

// Problem constants (fixed by setup_inputs)
#define Bsz 2
#define Sq  2048
#define Dm  1024
#define Hn  8
#define NEGV (-1e10f)

// Scratch (device globals; no allocations allowed)
__device__ float g_q[Bsz * Sq * Dm];        // 16 MB  q = x @ wi
__device__ float g_scores[Bsz * Sq * Sq];   // 32 MB  attention scores / probs
__device__ float g_head[Bsz * Sq * Dm];     // 16 MB  head = q + P@q ; later ffn act
__device__ float g_h[Bsz * Sq * Dm];        // 16 MB  h = head @ Weff
__device__ float g_weff[Dm * Dm];           // 4 MB   folded out_kernel

// ---------------------------------------------------------------------------
__global__ void fold_wout(const float* __restrict__ ok, float* __restrict__ w) {
    int i = blockIdx.x * 256 + threadIdx.x;
    float s = 0.f;
#pragma unroll
    for (int h = 0; h < Hn; h++) s += ok[(size_t)h * Dm * Dm + i];
    w[i] = s;
}

// ---------------------------------------------------------------------------
// tf32 tensor-core GEMM: C[M,N] = epilogue(A[M,K] @ B)
//   BT=false: B is [K,N] row-major (NN). BT=true: B is [N,K] row-major (NT).
//   CK=true:  K truncated at (blockRow+1)*BM (causal PV)
//   EPI: 0 plain | 1 scale+causal mask | 2 +residual | 3 +bias | 4 swish
// CTA tile 128x128x16, 8 warps (64x32 each), mma.m16n8k8.tf32.
// ---------------------------------------------------------------------------
#define BMm 128
#define BNn 128
#define BKk 16

__device__ __forceinline__ float tf32r(float x) {
    uint32_t u;
    asm("cvt.rna.tf32.f32 %0, %1;" : "=r"(u) : "f"(x));
    return __uint_as_float(u);
}

template <int EPI, bool BT, bool CK>
__global__ __launch_bounds__(256)
void tgemm(const float* __restrict__ A, const float* __restrict__ B,
           float* __restrict__ C, int M, int N, int K,
           long sA, long sB, long sC,
           float alpha, const float* __restrict__ bias,
           const float* __restrict__ resid, long sR)
{
    if (EPI == 1 && blockIdx.x > blockIdx.y) return;   // skip upper-tri score blocks

    const int bz = blockIdx.z;
    A += (size_t)bz * sA;
    B += (size_t)bz * sB;
    C += (size_t)bz * sC;

    const int m0 = blockIdx.y * BMm;
    const int n0 = blockIdx.x * BNn;
    int Keff = K;
    if (CK) Keff = min(K, (int)(blockIdx.y + 1) * BMm);

    // As: [m][k] stride 20 (conflict-free fragment loads; 2-way on stores)
    // Bs NN: [k][n] stride 136 ; Bs NT: [n][k] stride 20
    __shared__ float As[BMm * 20];
    __shared__ float Bs[BT ? (BNn * 20) : (BKk * 136)];

    const int t    = threadIdx.x;       // 0..255
    const int lane = t & 31;
    const int wid  = t >> 5;            // 0..7
    const int wRow = wid >> 2;          // 0..1 -> 64-row slab
    const int wCol = wid & 3;           // 0..3 -> 32-col slab
    const int g    = lane >> 2;         // 0..7
    const int c    = lane & 3;          // 0..3

    // loader indices
    const int aRow = t >> 2;            // 0..63
    const int aCol = (t & 3) << 2;      // 0,4,8,12
    const int bRow = t >> 5;            // 0..7   (NN)
    const int bCol = (t & 31) << 2;     // 0..124 (NN)

    float acc[4][4][4];
#pragma unroll
    for (int i = 0; i < 4; i++)
#pragma unroll
        for (int j = 0; j < 4; j++)
#pragma unroll
            for (int e = 0; e < 4; e++) acc[i][j][e] = 0.f;

    const uint32_t* Asu = (const uint32_t*)As;
    const uint32_t* Bsu = (const uint32_t*)Bs;

    for (int k0 = 0; k0 < Keff; k0 += BKk) {
        // ---- load A tile (128x16) ----
#pragma unroll
        for (int r = 0; r < 2; r++) {
            const int m = aRow + r * 64;
            float4 v = *(const float4*)&A[(size_t)(m0 + m) * K + k0 + aCol];
            float* d = &As[m * 20 + aCol];
            d[0] = tf32r(v.x); d[1] = tf32r(v.y); d[2] = tf32r(v.z); d[3] = tf32r(v.w);
        }
        // ---- load B tile ----
        if (BT) {   // B [N][K]; Bs[n][k] stride 20
#pragma unroll
            for (int r = 0; r < 2; r++) {
                const int n = aRow + r * 64;
                float4 v = *(const float4*)&B[(size_t)(n0 + n) * K + k0 + aCol];
                float* d = &Bs[n * 20 + aCol];
                d[0] = tf32r(v.x); d[1] = tf32r(v.y); d[2] = tf32r(v.z); d[3] = tf32r(v.w);
            }
        } else {    // B [K][N]; Bs[k][n] stride 136
#pragma unroll
            for (int r = 0; r < 2; r++) {
                const int k = bRow + r * 8;
                float4 v = *(const float4*)&B[(size_t)(k0 + k) * N + n0 + bCol];
                v.x = tf32r(v.x); v.y = tf32r(v.y); v.z = tf32r(v.z); v.w = tf32r(v.w);
                *(float4*)&Bs[k * 136 + bCol] = v;
            }
        }
        __syncthreads();

        // ---- compute: 2 k-steps of 8 ----
#pragma unroll
        for (int kk = 0; kk < 2; kk++) {
            const int kb = kk * 8;
            uint32_t af[4][4], bf[4][2];
#pragma unroll
            for (int mt = 0; mt < 4; mt++) {
                const int m = wRow * 64 + mt * 16 + g;
                const int k = kb + c;
                af[mt][0] = Asu[m * 20 + k];
                af[mt][1] = Asu[(m + 8) * 20 + k];
                af[mt][2] = Asu[m * 20 + k + 4];
                af[mt][3] = Asu[(m + 8) * 20 + k + 4];
            }
#pragma unroll
            for (int nt = 0; nt < 4; nt++) {
                const int n = wCol * 32 + nt * 8 + g;
                if (BT) {
                    bf[nt][0] = Bsu[n * 20 + kb + c];
                    bf[nt][1] = Bsu[n * 20 + kb + c + 4];
                } else {
                    bf[nt][0] = Bsu[(kb + c) * 136 + n];
                    bf[nt][1] = Bsu[(kb + c + 4) * 136 + n];
                }
            }
#pragma unroll
            for (int mt = 0; mt < 4; mt++)
#pragma unroll
                for (int nt = 0; nt < 4; nt++) {
                    float* d = acc[mt][nt];
                    asm volatile(
                        "mma.sync.aligned.m16n8k8.row.col.f32.tf32.tf32.f32 "
                        "{%0,%1,%2,%3}, {%4,%5,%6,%7}, {%8,%9}, {%0,%1,%2,%3};"
                        : "+f"(d[0]), "+f"(d[1]), "+f"(d[2]), "+f"(d[3])
                        : "r"(af[mt][0]), "r"(af[mt][1]), "r"(af[mt][2]), "r"(af[mt][3]),
                          "r"(bf[nt][0]), "r"(bf[nt][1]));
                }
        }
        __syncthreads();
    }

    // ---- epilogue ----
#pragma unroll
    for (int mt = 0; mt < 4; mt++) {
#pragma unroll
        for (int nt = 0; nt < 4; nt++) {
            const int row0 = m0 + wRow * 64 + mt * 16 + g;
            const int col0 = n0 + wCol * 32 + nt * 8 + 2 * c;
            float* d = acc[mt][nt];
#pragma unroll
            for (int half = 0; half < 2; half++) {
                const int row = row0 + half * 8;
                float v0 = d[half * 2 + 0];
                float v1 = d[half * 2 + 1];
                if (EPI == 1) {
                    v0 = (col0 <= row)     ? v0 * alpha : NEGV;
                    v1 = (col0 + 1 <= row) ? v1 * alpha : NEGV;
                }
                if (EPI == 2) {
                    const float* rr = resid + (size_t)bz * sR + (size_t)row * N + col0;
                    v0 += rr[0]; v1 += rr[1];
                }
                if (EPI == 3) { v0 += bias[col0]; v1 += bias[col0 + 1]; }
                if (EPI == 4) {
                    v0 = v0 / (1.f + __expf(-v0));
                    v1 = v1 / (1.f + __expf(-v1));
                }
                float2 o = make_float2(v0, v1);
                *(float2*)&C[(size_t)row * N + col0] = o;
            }
        }
    }
}

// ---------------------------------------------------------------------------
// Row softmax over causal prefix (row i valid length = roundup(i+1,128)).
// ---------------------------------------------------------------------------
__global__ void softmax_rows(float* __restrict__ sc) {
    const int rowg = blockIdx.x;
    const int b = rowg / Sq, r = rowg % Sq;
    float* p = sc + (size_t)b * Sq * Sq + (size_t)r * Sq;
    const int L = ((r >> 7) + 1) << 7;
    const int t = threadIdx.x;

    float vals[8];
    int cnt = 0;
    float mx = -INFINITY;
    for (int j = t; j < L; j += 256) { float v = p[j]; vals[cnt++] = v; mx = fmaxf(mx, v); }

    __shared__ float red[256];
    red[t] = mx; __syncthreads();
    for (int s = 128; s > 0; s >>= 1) { if (t < s) red[t] = fmaxf(red[t], red[t + s]); __syncthreads(); }
    mx = red[0]; __syncthreads();

    float sum = 0.f;
    for (int i = 0; i < cnt; i++) { vals[i] = __expf(vals[i] - mx); sum += vals[i]; }
    red[t] = sum; __syncthreads();
    for (int s = 128; s > 0; s >>= 1) { if (t < s) red[t] += red[t + s]; __syncthreads(); }
    const float inv = 1.f / red[0];

    cnt = 0;
    for (int j = t; j < L; j += 256) p[j] = vals[cnt++] * inv;
}

// ---------------------------------------------------------------------------
__global__ void layernorm_rows(float* __restrict__ h) {
    const int row = blockIdx.x;
    float* p = h + (size_t)row * Dm;
    const int t = threadIdx.x;
    float4 v = *(float4*)&p[t * 4];
    float s  = v.x + v.y + v.z + v.w;
    float sq = v.x * v.x + v.y * v.y + v.z * v.z + v.w * v.w;

    __shared__ float rs[256], rq[256];
    rs[t] = s; rq[t] = sq; __syncthreads();
    for (int k = 128; k > 0; k >>= 1) {
        if (t < k) { rs[t] += rs[t + k]; rq[t] += rq[t + k]; }
        __syncthreads();
    }
    const float mean = rs[0] * (1.f / Dm);
    const float var  = rq[0] * (1.f / Dm) - mean * mean;
    const float inv  = rsqrtf(var + 1e-5f);
    v.x = (v.x - mean) * inv;
    v.y = (v.y - mean) * inv;
    v.z = (v.z - mean) * inv;
    v.w = (v.w - mean) * inv;
    *(float4*)&p[t * 4] = v;
}

// ---------------------------------------------------------------------------
extern "C" void kernel_launch(void* const* d_in, const int* in_sizes, int n_in,
                              void* d_out, int out_size)
{
    const float* x  = (const float*)d_in[0];   // [B,S,D]
    // d_in[1] = mask (causal tril; structure hardcoded)
    const float* wi = (const float*)d_in[2];   // [D,D]
    const float* ok = (const float*)d_in[3];   // [H*D,D]
    const float* ob = (const float*)d_in[4];   // [D]
    float* out = (float*)d_out;                // [B,S,D]

    float *q, *sc, *head, *h, *weff;
    cudaGetSymbolAddress((void**)&q,    g_q);
    cudaGetSymbolAddress((void**)&sc,   g_scores);
    cudaGetSymbolAddress((void**)&head, g_head);
    cudaGetSymbolAddress((void**)&h,    g_h);
    cudaGetSymbolAddress((void**)&weff, g_weff);

    const int MS = Bsz * Sq;          // 4096
    const long sQ  = (long)Sq * Dm;
    const long sSS = (long)Sq * Sq;

    // 1. fold out_kernel
    fold_wout<<<(Dm * Dm) / 256, 256>>>(ok, weff);

    // 2. q = x @ wi
    tgemm<0, false, false><<<dim3(Dm / BNn, MS / BMm, 1), 256>>>(
        x, wi, q, MS, Dm, Dm, 0, 0, 0, 0.f, nullptr, nullptr, 0);

    // 3. scores = (q @ q^T)/32, causal-masked, lower-tri blocks only
    tgemm<1, true, false><<<dim3(Sq / BNn, Sq / BMm, Bsz), 256>>>(
        q, q, sc, Sq, Sq, Dm, sQ, sQ, sSS, 1.f / 32.f, nullptr, nullptr, 0);

    // 4. softmax
    softmax_rows<<<Bsz * Sq, 256>>>(sc);

    // 5. head = P @ q + q (causal K truncation)
    tgemm<2, false, true><<<dim3(Dm / BNn, Sq / BMm, Bsz), 256>>>(
        sc, q, head, Sq, Dm, Sq, sSS, sQ, sQ, 0.f, nullptr, q, sQ);

    // 6. h = head @ Weff + bias
    tgemm<3, false, false><<<dim3(Dm / BNn, MS / BMm, 1), 256>>>(
        head, weff, h, MS, Dm, Dm, 0, 0, 0, 0.f, ob, nullptr, 0);

    // 7. layernorm
    layernorm_rows<<<Bsz * Sq, 256>>>(h);

    // 8. act = swish(h @ wi)
    tgemm<4, false, false><<<dim3(Dm / BNn, MS / BMm, 1), 256>>>(
        h, wi, head, MS, Dm, Dm, 0, 0, 0, 0.f, nullptr, nullptr, 0);

    // 9. out = act @ wi
    tgemm<0, false, false><<<dim3(Dm / BNn, MS / BMm, 1), 256>>>(
        head, wi, out, MS, Dm, Dm, 0, 0, 0, 0.f, nullptr, nullptr, 0);
}

// round 5
// speedup vs baseline: 2.7266x; 1.0480x over previous
#include <cuda_runtime.h>
#include <math.h>
#include <stdint.h>

#define Bsz 2
#define Sq  2048
#define Dm  1024
#define Hn  8
#define NEGV (-1e10f)

// Scratch (device globals; no allocations allowed)
__device__ float g_xr[Bsz * Sq * Dm];       // tf32-rounded x
__device__ float g_q[Bsz * Sq * Dm];        // q = x @ wi (tf32-rounded)
__device__ float g_qT[Bsz * Sq * Dm];       // q transposed per batch [D][S]
__device__ float g_scores[Bsz * Sq * Sq];   // scores / probs
__device__ float g_head[Bsz * Sq * Dm];     // head ; later ffn act
__device__ float g_h[Bsz * Sq * Dm];        // h
__device__ float g_weffT[Dm * Dm];          // folded+transposed out_kernel
__device__ float g_wiT[Dm * Dm];            // wi transposed

// ---------------- helpers ----------------
__device__ __forceinline__ float tf32r(float x) {
    uint32_t u;
    asm("cvt.rna.tf32.f32 %0, %1;" : "=r"(u) : "f"(x));
    return __uint_as_float(u);
}
__device__ __forceinline__ uint32_t smem_u32(const void* p) {
    uint32_t a;
    asm("{ .reg .u64 t; cvta.to.shared.u64 t, %1; cvt.u32.u64 %0, t; }" : "=r"(a) : "l"(p));
    return a;
}
#define CPA(d, s)  asm volatile("cp.async.cg.shared.global [%0], [%1], 16;" :: "r"(d), "l"(s) : "memory")
#define CPC()      asm volatile("cp.async.commit_group;" ::: "memory")
#define CPW(n)     asm volatile("cp.async.wait_group %0;" :: "n"(n) : "memory")

// ---------------------------------------------------------------------------
// tf32 mma.sync GEMM, 4-stage cp.async pipeline.
// C[M,N] = epi(A[M,K] @ B^T), B stored [N][K] row-major (all operands NT).
// Operands are ALREADY tf32-rounded in gmem (producers round).
// EPI: 0 plain | 1 scale+causal | 2 +residual | 3 +bias | 4 swish
// CK: truncate K at (blockRow+1)*128.  RND: tf32-round the stored output.
// CTA 128x128, 8 warps (2x4), warp tile 64x32, mma.m16n8k8.
// smem per stage: A 128x20f (10240B), B 128x20f (10240B); 4 stages = 80KB.
// ---------------------------------------------------------------------------
#define TILE 128
#define BKk  16
#define ASZ  10240
#define NSTG 4
#define DSMEM (2 * NSTG * ASZ)

template <int EPI, bool CK, bool RND>
__global__ __launch_bounds__(256, 2)
void tgemm(const float* __restrict__ A, const float* __restrict__ B,
           float* __restrict__ C, int M, int N, int K,
           long sA, long sB, long sC, float alpha,
           const float* __restrict__ bias, const float* __restrict__ resid, long sR)
{
    if (EPI == 1 && blockIdx.x > blockIdx.y) return;
    const int bz = blockIdx.z;
    A += (size_t)bz * sA;  B += (size_t)bz * sB;  C += (size_t)bz * sC;
    const int m0 = blockIdx.y * TILE;
    const int n0 = blockIdx.x * TILE;
    const int Keff = CK ? min(K, (int)(blockIdx.y + 1) * TILE) : K;
    const int NK = Keff / BKk;

    extern __shared__ char smb[];
    const uint32_t smA = smem_u32(smb);
    const uint32_t smB = smA + NSTG * ASZ;

    const int t    = threadIdx.x;
    const int lane = t & 31;
    const int wid  = t >> 5;
    const int wRow = wid >> 2;        // 0..1
    const int wCol = wid & 3;         // 0..3
    const int g    = lane >> 2;       // 0..7
    const int c    = lane & 3;        // 0..3

    const int lrow  = t >> 2;         // 0..63
    const int lchnk = t & 3;          // 0..3 (16B chunk within 64B k-slice)

    // issue cp.async loads for one 128x16 tile pair at k-chunk kc
    auto load_stage = [&](int s, int kc) {
        const uint32_t da = smA + s * ASZ;
        const uint32_t db = smB + s * ASZ;
#pragma unroll
        for (int r = 0; r < 2; r++) {
            const int row = lrow + r * 64;
            CPA(da + row * 80 + lchnk * 16,
                A + (size_t)(m0 + row) * K + kc * BKk + lchnk * 4);
            CPA(db + row * 80 + lchnk * 16,
                B + (size_t)(n0 + row) * K + kc * BKk + lchnk * 4);
        }
    };

    float acc[4][4][4];
#pragma unroll
    for (int i = 0; i < 4; i++)
#pragma unroll
        for (int j = 0; j < 4; j++)
#pragma unroll
            for (int e = 0; e < 4; e++) acc[i][j][e] = 0.f;

    // prologue: stages 0..2
#pragma unroll
    for (int s = 0; s < NSTG - 1; s++) { load_stage(s, s); CPC(); }

    for (int it = 0; it < NK; it++) {
        CPW(2);              // own groups: chunk `it` complete
        __syncthreads();     // everyone's chunk `it` visible; buf (it-1)%4 free
        if (it + NSTG - 1 < NK) load_stage((it + NSTG - 1) & (NSTG - 1), it + NSTG - 1);
        CPC();               // always commit (keeps group arithmetic uniform)

        const int s = it & (NSTG - 1);
        const uint32_t* Asu = (const uint32_t*)(smb + (size_t)s * ASZ);
        const uint32_t* Bsu = (const uint32_t*)(smb + (size_t)(NSTG + s) * ASZ);

#pragma unroll
        for (int kk = 0; kk < 2; kk++) {
            const int kb = kk * 8;
            uint32_t af[4][4], bf[4][2];
#pragma unroll
            for (int mt = 0; mt < 4; mt++) {
                const int m = wRow * 64 + mt * 16 + g;
                const int k = kb + c;
                af[mt][0] = Asu[m * 20 + k];
                af[mt][1] = Asu[(m + 8) * 20 + k];
                af[mt][2] = Asu[m * 20 + k + 4];
                af[mt][3] = Asu[(m + 8) * 20 + k + 4];
            }
#pragma unroll
            for (int nt = 0; nt < 4; nt++) {
                const int n = wCol * 32 + nt * 8 + g;
                bf[nt][0] = Bsu[n * 20 + kb + c];
                bf[nt][1] = Bsu[n * 20 + kb + c + 4];
            }
#pragma unroll
            for (int mt = 0; mt < 4; mt++)
#pragma unroll
                for (int nt = 0; nt < 4; nt++) {
                    float* d = acc[mt][nt];
                    asm volatile(
                        "mma.sync.aligned.m16n8k8.row.col.f32.tf32.tf32.f32 "
                        "{%0,%1,%2,%3}, {%4,%5,%6,%7}, {%8,%9}, {%0,%1,%2,%3};"
                        : "+f"(d[0]), "+f"(d[1]), "+f"(d[2]), "+f"(d[3])
                        : "r"(af[mt][0]), "r"(af[mt][1]), "r"(af[mt][2]), "r"(af[mt][3]),
                          "r"(bf[nt][0]), "r"(bf[nt][1]));
                }
        }
    }

    // ---- epilogue ----
#pragma unroll
    for (int mt = 0; mt < 4; mt++) {
#pragma unroll
        for (int nt = 0; nt < 4; nt++) {
            const int row0 = m0 + wRow * 64 + mt * 16 + g;
            const int col0 = n0 + wCol * 32 + nt * 8 + 2 * c;
            float* d = acc[mt][nt];
#pragma unroll
            for (int half = 0; half < 2; half++) {
                const int row = row0 + half * 8;
                float v0 = d[half * 2 + 0];
                float v1 = d[half * 2 + 1];
                if (EPI == 1) {
                    v0 = (col0 <= row)     ? v0 * alpha : NEGV;
                    v1 = (col0 + 1 <= row) ? v1 * alpha : NEGV;
                }
                if (EPI == 2) {
                    const float* rr = resid + (size_t)bz * sR + (size_t)row * N + col0;
                    v0 += rr[0]; v1 += rr[1];
                }
                if (EPI == 3) { v0 += bias[col0]; v1 += bias[col0 + 1]; }
                if (EPI == 4) {
                    v0 = v0 / (1.f + __expf(-v0));
                    v1 = v1 / (1.f + __expf(-v1));
                }
                if (RND) { v0 = tf32r(v0); v1 = tf32r(v1); }
                *(float2*)&C[(size_t)row * N + col0] = make_float2(v0, v1);
            }
        }
    }
}

// ---------------------------------------------------------------------------
__global__ void round_copy(const float* __restrict__ in, float* __restrict__ out) {
    const int i = (blockIdx.x * 256 + threadIdx.x) * 4;
    float4 v = *(const float4*)(in + i);
    v.x = tf32r(v.x); v.y = tf32r(v.y); v.z = tf32r(v.z); v.w = tf32r(v.w);
    *(float4*)(out + i) = v;
}

// Tiled transpose with tf32 rounding: out[c][r] = round(in[r][c])
__global__ void transpose_b(const float* __restrict__ in, float* __restrict__ out,
                            int R, int C, long sI, long sO) {
    __shared__ float tile[32][33];
    const float* I = in  + (size_t)blockIdx.z * sI;
    float*       O = out + (size_t)blockIdx.z * sO;
    const int r0 = blockIdx.y * 32, c0 = blockIdx.x * 32;
    const int tx = threadIdx.x, ty = threadIdx.y;
#pragma unroll
    for (int j = 0; j < 4; j++)
        tile[ty + j * 8][tx] = tf32r(I[(size_t)(r0 + ty + j * 8) * C + c0 + tx]);
    __syncthreads();
#pragma unroll
    for (int j = 0; j < 4; j++)
        O[(size_t)(c0 + ty + j * 8) * R + r0 + tx] = tile[tx][ty + j * 8];
}

// out[n][k] = round(sum_h ok[h*D*D + k*D + n])
__global__ void fold_transpose(const float* __restrict__ ok, float* __restrict__ out) {
    __shared__ float tile[32][33];
    const int k0 = blockIdx.x * 32, n0 = blockIdx.y * 32;
    const int tx = threadIdx.x, ty = threadIdx.y;
    float acc[4] = {0.f, 0.f, 0.f, 0.f};
    for (int h = 0; h < Hn; h++)
#pragma unroll
        for (int j = 0; j < 4; j++)
            acc[j] += ok[(size_t)h * Dm * Dm + (size_t)(k0 + ty + 8 * j) * Dm + n0 + tx];
#pragma unroll
    for (int j = 0; j < 4; j++) tile[ty + 8 * j][tx] = tf32r(acc[j]);
    __syncthreads();
#pragma unroll
    for (int j = 0; j < 4; j++)
        out[(size_t)(n0 + ty + 8 * j) * Dm + k0 + tx] = tile[tx][ty + 8 * j];
}

// ---------------------------------------------------------------------------
// Row softmax over causal prefix; writes tf32-rounded probabilities.
// ---------------------------------------------------------------------------
__global__ void softmax_rows(float* __restrict__ sc) {
    const int rowg = blockIdx.x;
    const int b = rowg / Sq, r = rowg % Sq;
    float* p = sc + (size_t)b * Sq * Sq + (size_t)r * Sq;
    const int L = ((r >> 7) + 1) << 7;
    const int t = threadIdx.x;

    float vals[8];
    int cnt = 0;
    float mx = -INFINITY;
    for (int j = t; j < L; j += 256) { float v = p[j]; vals[cnt++] = v; mx = fmaxf(mx, v); }

    __shared__ float red[256];
    red[t] = mx; __syncthreads();
    for (int s = 128; s > 0; s >>= 1) { if (t < s) red[t] = fmaxf(red[t], red[t + s]); __syncthreads(); }
    mx = red[0]; __syncthreads();

    float sum = 0.f;
    for (int i = 0; i < cnt; i++) { vals[i] = __expf(vals[i] - mx); sum += vals[i]; }
    red[t] = sum; __syncthreads();
    for (int s = 128; s > 0; s >>= 1) { if (t < s) red[t] += red[t + s]; __syncthreads(); }
    const float inv = 1.f / red[0];

    cnt = 0;
    for (int j = t; j < L; j += 256) p[j] = tf32r(vals[cnt++] * inv);
}

// LayerNorm; writes tf32-rounded output (input to next GEMM).
__global__ void layernorm_rows(float* __restrict__ h) {
    const int row = blockIdx.x;
    float* p = h + (size_t)row * Dm;
    const int t = threadIdx.x;
    float4 v = *(float4*)&p[t * 4];
    float s  = v.x + v.y + v.z + v.w;
    float sq = v.x * v.x + v.y * v.y + v.z * v.z + v.w * v.w;

    __shared__ float rs[256], rq[256];
    rs[t] = s; rq[t] = sq; __syncthreads();
    for (int k = 128; k > 0; k >>= 1) {
        if (t < k) { rs[t] += rs[t + k]; rq[t] += rq[t + k]; }
        __syncthreads();
    }
    const float mean = rs[0] * (1.f / Dm);
    const float var  = rq[0] * (1.f / Dm) - mean * mean;
    const float inv  = rsqrtf(var + 1e-5f);
    v.x = tf32r((v.x - mean) * inv);
    v.y = tf32r((v.y - mean) * inv);
    v.z = tf32r((v.z - mean) * inv);
    v.w = tf32r((v.w - mean) * inv);
    *(float4*)&p[t * 4] = v;
}

// ---------------------------------------------------------------------------
extern "C" void kernel_launch(void* const* d_in, const int* in_sizes, int n_in,
                              void* d_out, int out_size)
{
    const float* x  = (const float*)d_in[0];
    const float* wi = (const float*)d_in[2];
    const float* ok = (const float*)d_in[3];
    const float* ob = (const float*)d_in[4];
    float* out = (float*)d_out;

    float *xr, *q, *qT, *sc, *head, *h, *weffT, *wiT;
    cudaGetSymbolAddress((void**)&xr,    g_xr);
    cudaGetSymbolAddress((void**)&q,     g_q);
    cudaGetSymbolAddress((void**)&qT,    g_qT);
    cudaGetSymbolAddress((void**)&sc,    g_scores);
    cudaGetSymbolAddress((void**)&head,  g_head);
    cudaGetSymbolAddress((void**)&h,     g_h);
    cudaGetSymbolAddress((void**)&weffT, g_weffT);
    cudaGetSymbolAddress((void**)&wiT,   g_wiT);

    cudaFuncSetAttribute(tgemm<0, false, true>,  cudaFuncAttributeMaxDynamicSharedMemorySize, DSMEM);
    cudaFuncSetAttribute(tgemm<1, false, false>, cudaFuncAttributeMaxDynamicSharedMemorySize, DSMEM);
    cudaFuncSetAttribute(tgemm<2, true,  true>,  cudaFuncAttributeMaxDynamicSharedMemorySize, DSMEM);
    cudaFuncSetAttribute(tgemm<3, false, false>, cudaFuncAttributeMaxDynamicSharedMemorySize, DSMEM);
    cudaFuncSetAttribute(tgemm<4, false, true>,  cudaFuncAttributeMaxDynamicSharedMemorySize, DSMEM);
    cudaFuncSetAttribute(tgemm<0, false, false>, cudaFuncAttributeMaxDynamicSharedMemorySize, DSMEM);

    const int MS = Bsz * Sq;            // 4096
    const long sQ  = (long)Sq * Dm;
    const long sSS = (long)Sq * Sq;

    // producers: round everything feeding a GEMM to tf32
    round_copy<<<(Bsz * Sq * Dm) / 1024, 256>>>(x, xr);
    fold_transpose<<<dim3(Dm / 32, Dm / 32), dim3(32, 8)>>>(ok, weffT);
    transpose_b<<<dim3(Dm / 32, Dm / 32, 1), dim3(32, 8)>>>(wi, wiT, Dm, Dm, 0, 0);

    // q = x @ wi  (rounded output)
    tgemm<0, false, true><<<dim3(Dm / TILE, MS / TILE, 1), 256, DSMEM>>>(
        xr, wiT, q, MS, Dm, Dm, 0, 0, 0, 0.f, nullptr, nullptr, 0);

    // qT per batch (already rounded; transpose rounding is idempotent)
    transpose_b<<<dim3(Dm / 32, Sq / 32, Bsz), dim3(32, 8)>>>(q, qT, Sq, Dm, sQ, sQ);

    // scores = (q @ q^T)/32 causal (full-precision scores; softmax rounds probs)
    tgemm<1, false, false><<<dim3(Sq / TILE, Sq / TILE, Bsz), 256, DSMEM>>>(
        q, q, sc, Sq, Sq, Dm, sQ, sQ, sSS, 1.f / 32.f, nullptr, nullptr, 0);

    softmax_rows<<<Bsz * Sq, 256>>>(sc);

    // head = P @ q + q  (rounded output; causal K truncation)
    tgemm<2, true, true><<<dim3(Dm / TILE, Sq / TILE, Bsz), 256, DSMEM>>>(
        sc, qT, head, Sq, Dm, Sq, sSS, sQ, sQ, 0.f, nullptr, q, sQ);

    // h = head @ Weff + bias (full precision; LN rounds its output)
    tgemm<3, false, false><<<dim3(Dm / TILE, MS / TILE, 1), 256, DSMEM>>>(
        head, weffT, h, MS, Dm, Dm, 0, 0, 0, 0.f, ob, nullptr, 0);

    layernorm_rows<<<Bsz * Sq, 256>>>(h);

    // act = swish(h @ wi) (rounded output)
    tgemm<4, false, true><<<dim3(Dm / TILE, MS / TILE, 1), 256, DSMEM>>>(
        h, wiT, head, MS, Dm, Dm, 0, 0, 0, 0.f, nullptr, nullptr, 0);

    // out = act @ wi (final output: NOT rounded)
    tgemm<0, false, false><<<dim3(Dm / TILE, MS / TILE, 1), 256, DSMEM>>>(
        head, wiT, out, MS, Dm, Dm, 0, 0, 0, 0.f, nullptr, nullptr, 0);
}

// round 6
// speedup vs baseline: 3.6574x; 1.3414x over previous
#include <cuda_runtime.h>
#include <math.h>
#include <stdint.h>

#define Bsz 2
#define Sq  2048
#define Dm  1024
#define Hn  8
#define NEGV (-1e10f)

// Scratch (device globals; no allocations allowed)
__device__ float g_xr[Bsz * Sq * Dm];       // tf32-rounded x
__device__ float g_q[Bsz * Sq * Dm];        // q (tf32-rounded)
__device__ float g_qT[Bsz * Sq * Dm];       // q transposed per batch [D][S]
__device__ float g_scores[Bsz * Sq * Sq];   // scores / probs
__device__ float g_head[Bsz * Sq * Dm];     // head ; later ffn act
__device__ float g_h[Bsz * Sq * Dm];        // h
__device__ float g_weffT[Dm * Dm];          // folded+transposed out_kernel
__device__ float g_wiT[Dm * Dm];            // wi transposed

// ---------------- helpers ----------------
__device__ __forceinline__ float tf32r(float x) {
    uint32_t u;
    asm("cvt.rna.tf32.f32 %0, %1;" : "=r"(u) : "f"(x));
    return __uint_as_float(u);
}
__device__ __forceinline__ uint32_t smem_u32(const void* p) {
    uint32_t a;
    asm("{ .reg .u64 t; cvta.to.shared.u64 t, %1; cvt.u32.u64 %0, t; }" : "=r"(a) : "l"(p));
    return a;
}
#define CPA(d, s)  asm volatile("cp.async.cg.shared.global [%0], [%1], 16;" :: "r"(d), "l"(s) : "memory")
#define CPC()      asm volatile("cp.async.commit_group;" ::: "memory")
#define CPW(n)     asm volatile("cp.async.wait_group %0;" :: "n"(n) : "memory")
#define LDSM4(r0, r1, r2, r3, a) \
    asm volatile("ldmatrix.sync.aligned.m8n8.x4.shared.b16 {%0,%1,%2,%3}, [%4];" \
        : "=r"(r0), "=r"(r1), "=r"(r2), "=r"(r3) : "r"(a))

// ---------------------------------------------------------------------------
// tf32 mma.sync GEMM, 4-stage cp.async pipeline, ldmatrix fragment feed.
// C[M,N] = epi(A[M,K] @ B^T), B stored [N][K] row-major (all operands NT).
// Smem stage layout: 128 rows x 64B (16 tf32); physChunk = chunk ^ ((row>>1)&3).
// EPI: 0 plain | 1 scale+causal | 2 +residual | 3 +bias | 4 swish
// CK: truncate K at (blockRow+1)*128.  RND: tf32-round stored output.
// CTA 128x128, 8 warps (2x4), warp tile 64x32, mma.m16n8k8.
// ---------------------------------------------------------------------------
#define TILE 128
#define BKk  16
#define ASZ  8192
#define NSTG 4
#define DSMEM (2 * NSTG * ASZ)

template <int EPI, bool CK, bool RND>
__global__ __launch_bounds__(256, 2)
void tgemm(const float* __restrict__ A, const float* __restrict__ B,
           float* __restrict__ C, int M, int N, int K,
           long sA, long sB, long sC, float alpha,
           const float* __restrict__ bias, const float* __restrict__ resid, long sR)
{
    if (EPI == 1 && blockIdx.x > blockIdx.y) return;
    const int bz = blockIdx.z;
    A += (size_t)bz * sA;  B += (size_t)bz * sB;  C += (size_t)bz * sC;
    const int m0 = blockIdx.y * TILE;
    const int n0 = blockIdx.x * TILE;
    const int Keff = CK ? min(K, (int)(blockIdx.y + 1) * TILE) : K;
    const int NK = Keff / BKk;

    extern __shared__ char smb[];
    const uint32_t smA = smem_u32(smb);
    const uint32_t smB = smA + NSTG * ASZ;

    const int t    = threadIdx.x;
    const int lane = t & 31;
    const int wid  = t >> 5;
    const int wRow = wid >> 2;        // 0..1
    const int wCol = wid & 3;         // 0..3

    // loader: thread -> (row = t>>2 [+64], chunk = t&3)
    const int lrow  = t >> 2;
    const int lchnk = t & 3;

    auto load_stage = [&](int s, int kc) {
        const uint32_t da = smA + s * ASZ;
        const uint32_t db = smB + s * ASZ;
#pragma unroll
        for (int r = 0; r < 2; r++) {
            const int row  = lrow + r * 64;
            const int phys = lchnk ^ ((row >> 1) & 3);
            CPA(da + row * 64 + phys * 16,
                A + (size_t)(m0 + row) * K + kc * BKk + lchnk * 4);
            CPA(db + row * 64 + phys * 16,
                B + (size_t)(n0 + row) * K + kc * BKk + lchnk * 4);
        }
    };

    // ldmatrix per-lane source rows/chunk-halves (lane-constant across iters)
    const int aRowOff = (lane & 7) + ((lane >> 3) & 1) * 8;  // within 16-row block
    const int aChHalf = lane >> 4;                            // 0..1
    const int bRowOff = ((lane >> 4) & 1) * 8 + (lane & 7);   // within 16-row pair
    const int bChHalf = (lane >> 3) & 1;                      // 0..1

    float acc[4][4][4];
#pragma unroll
    for (int i = 0; i < 4; i++)
#pragma unroll
        for (int j = 0; j < 4; j++)
#pragma unroll
            for (int e = 0; e < 4; e++) acc[i][j][e] = 0.f;

#pragma unroll
    for (int s = 0; s < NSTG - 1; s++) { load_stage(s, s); CPC(); }

    for (int it = 0; it < NK; it++) {
        CPW(2);
        __syncthreads();
        if (it + NSTG - 1 < NK) load_stage((it + NSTG - 1) & (NSTG - 1), it + NSTG - 1);
        CPC();

        const int s = it & (NSTG - 1);
        const uint32_t aBase = smA + s * ASZ;
        const uint32_t bBase = smB + s * ASZ;

#pragma unroll
        for (int kk = 0; kk < 2; kk++) {
            const int kb4 = kk * 2;          // k-chunk pair base (chunks of 4 floats)
            uint32_t af[4][4], bf[4][2];
#pragma unroll
            for (int mt = 0; mt < 4; mt++) {
                const int row   = wRow * 64 + mt * 16 + aRowOff;
                const int chunk = kb4 + aChHalf;
                const uint32_t addr = aBase + row * 64 + ((chunk ^ ((row >> 1) & 3)) << 4);
                LDSM4(af[mt][0], af[mt][1], af[mt][2], af[mt][3], addr);
            }
#pragma unroll
            for (int p = 0; p < 2; p++) {
                const int row   = wCol * 32 + p * 16 + bRowOff;
                const int chunk = kb4 + bChHalf;
                const uint32_t addr = bBase + row * 64 + ((chunk ^ ((row >> 1) & 3)) << 4);
                LDSM4(bf[2 * p][0], bf[2 * p][1], bf[2 * p + 1][0], bf[2 * p + 1][1], addr);
            }
#pragma unroll
            for (int mt = 0; mt < 4; mt++)
#pragma unroll
                for (int nt = 0; nt < 4; nt++) {
                    float* d = acc[mt][nt];
                    asm volatile(
                        "mma.sync.aligned.m16n8k8.row.col.f32.tf32.tf32.f32 "
                        "{%0,%1,%2,%3}, {%4,%5,%6,%7}, {%8,%9}, {%0,%1,%2,%3};"
                        : "+f"(d[0]), "+f"(d[1]), "+f"(d[2]), "+f"(d[3])
                        : "r"(af[mt][0]), "r"(af[mt][1]), "r"(af[mt][2]), "r"(af[mt][3]),
                          "r"(bf[nt][0]), "r"(bf[nt][1]));
                }
        }
    }

    // ---- epilogue ----
    const int g = lane >> 2;
    const int c = lane & 3;
#pragma unroll
    for (int mt = 0; mt < 4; mt++) {
#pragma unroll
        for (int nt = 0; nt < 4; nt++) {
            const int row0 = m0 + wRow * 64 + mt * 16 + g;
            const int col0 = n0 + wCol * 32 + nt * 8 + 2 * c;
            float* d = acc[mt][nt];
#pragma unroll
            for (int half = 0; half < 2; half++) {
                const int row = row0 + half * 8;
                float v0 = d[half * 2 + 0];
                float v1 = d[half * 2 + 1];
                if (EPI == 1) {
                    v0 = (col0 <= row)     ? v0 * alpha : NEGV;
                    v1 = (col0 + 1 <= row) ? v1 * alpha : NEGV;
                }
                if (EPI == 2) {
                    const float* rr = resid + (size_t)bz * sR + (size_t)row * N + col0;
                    v0 += rr[0]; v1 += rr[1];
                }
                if (EPI == 3) { v0 += bias[col0]; v1 += bias[col0 + 1]; }
                if (EPI == 4) {
                    v0 = v0 / (1.f + __expf(-v0));
                    v1 = v1 / (1.f + __expf(-v1));
                }
                if (RND) { v0 = tf32r(v0); v1 = tf32r(v1); }
                *(float2*)&C[(size_t)row * N + col0] = make_float2(v0, v1);
            }
        }
    }
}

// ---------------------------------------------------------------------------
__global__ void round_copy(const float* __restrict__ in, float* __restrict__ out) {
    const int i = (blockIdx.x * 256 + threadIdx.x) * 4;
    float4 v = *(const float4*)(in + i);
    v.x = tf32r(v.x); v.y = tf32r(v.y); v.z = tf32r(v.z); v.w = tf32r(v.w);
    *(float4*)(out + i) = v;
}

// Tiled transpose with tf32 rounding: out[c][r] = round(in[r][c])
__global__ void transpose_b(const float* __restrict__ in, float* __restrict__ out,
                            int R, int C, long sI, long sO) {
    __shared__ float tile[32][33];
    const float* I = in  + (size_t)blockIdx.z * sI;
    float*       O = out + (size_t)blockIdx.z * sO;
    const int r0 = blockIdx.y * 32, c0 = blockIdx.x * 32;
    const int tx = threadIdx.x, ty = threadIdx.y;
#pragma unroll
    for (int j = 0; j < 4; j++)
        tile[ty + j * 8][tx] = tf32r(I[(size_t)(r0 + ty + j * 8) * C + c0 + tx]);
    __syncthreads();
#pragma unroll
    for (int j = 0; j < 4; j++)
        O[(size_t)(c0 + ty + j * 8) * R + r0 + tx] = tile[tx][ty + j * 8];
}

// out[n][k] = round(sum_h ok[h*D*D + k*D + n])
__global__ void fold_transpose(const float* __restrict__ ok, float* __restrict__ out) {
    __shared__ float tile[32][33];
    const int k0 = blockIdx.x * 32, n0 = blockIdx.y * 32;
    const int tx = threadIdx.x, ty = threadIdx.y;
    float acc[4] = {0.f, 0.f, 0.f, 0.f};
    for (int h = 0; h < Hn; h++)
#pragma unroll
        for (int j = 0; j < 4; j++)
            acc[j] += ok[(size_t)h * Dm * Dm + (size_t)(k0 + ty + 8 * j) * Dm + n0 + tx];
#pragma unroll
    for (int j = 0; j < 4; j++) tile[ty + 8 * j][tx] = tf32r(acc[j]);
    __syncthreads();
#pragma unroll
    for (int j = 0; j < 4; j++)
        out[(size_t)(n0 + ty + 8 * j) * Dm + k0 + tx] = tile[tx][ty + 8 * j];
}

// ---------------------------------------------------------------------------
__global__ void softmax_rows(float* __restrict__ sc) {
    const int rowg = blockIdx.x;
    const int b = rowg / Sq, r = rowg % Sq;
    float* p = sc + (size_t)b * Sq * Sq + (size_t)r * Sq;
    const int L = ((r >> 7) + 1) << 7;
    const int t = threadIdx.x;

    float vals[8];
    int cnt = 0;
    float mx = -INFINITY;
    for (int j = t; j < L; j += 256) { float v = p[j]; vals[cnt++] = v; mx = fmaxf(mx, v); }

    __shared__ float red[256];
    red[t] = mx; __syncthreads();
    for (int s = 128; s > 0; s >>= 1) { if (t < s) red[t] = fmaxf(red[t], red[t + s]); __syncthreads(); }
    mx = red[0]; __syncthreads();

    float sum = 0.f;
    for (int i = 0; i < cnt; i++) { vals[i] = __expf(vals[i] - mx); sum += vals[i]; }
    red[t] = sum; __syncthreads();
    for (int s = 128; s > 0; s >>= 1) { if (t < s) red[t] += red[t + s]; __syncthreads(); }
    const float inv = 1.f / red[0];

    cnt = 0;
    for (int j = t; j < L; j += 256) p[j] = tf32r(vals[cnt++] * inv);
}

__global__ void layernorm_rows(float* __restrict__ h) {
    const int row = blockIdx.x;
    float* p = h + (size_t)row * Dm;
    const int t = threadIdx.x;
    float4 v = *(float4*)&p[t * 4];
    float s  = v.x + v.y + v.z + v.w;
    float sq = v.x * v.x + v.y * v.y + v.z * v.z + v.w * v.w;

    __shared__ float rs[256], rq[256];
    rs[t] = s; rq[t] = sq; __syncthreads();
    for (int k = 128; k > 0; k >>= 1) {
        if (t < k) { rs[t] += rs[t + k]; rq[t] += rq[t + k]; }
        __syncthreads();
    }
    const float mean = rs[0] * (1.f / Dm);
    const float var  = rq[0] * (1.f / Dm) - mean * mean;
    const float inv  = rsqrtf(var + 1e-5f);
    v.x = tf32r((v.x - mean) * inv);
    v.y = tf32r((v.y - mean) * inv);
    v.z = tf32r((v.z - mean) * inv);
    v.w = tf32r((v.w - mean) * inv);
    *(float4*)&p[t * 4] = v;
}

// ---------------------------------------------------------------------------
extern "C" void kernel_launch(void* const* d_in, const int* in_sizes, int n_in,
                              void* d_out, int out_size)
{
    const float* x  = (const float*)d_in[0];
    const float* wi = (const float*)d_in[2];
    const float* ok = (const float*)d_in[3];
    const float* ob = (const float*)d_in[4];
    float* out = (float*)d_out;

    float *xr, *q, *qT, *sc, *head, *h, *weffT, *wiT;
    cudaGetSymbolAddress((void**)&xr,    g_xr);
    cudaGetSymbolAddress((void**)&q,     g_q);
    cudaGetSymbolAddress((void**)&qT,    g_qT);
    cudaGetSymbolAddress((void**)&sc,    g_scores);
    cudaGetSymbolAddress((void**)&head,  g_head);
    cudaGetSymbolAddress((void**)&h,     g_h);
    cudaGetSymbolAddress((void**)&weffT, g_weffT);
    cudaGetSymbolAddress((void**)&wiT,   g_wiT);

    cudaFuncSetAttribute(tgemm<0, false, true>,  cudaFuncAttributeMaxDynamicSharedMemorySize, DSMEM);
    cudaFuncSetAttribute(tgemm<1, false, false>, cudaFuncAttributeMaxDynamicSharedMemorySize, DSMEM);
    cudaFuncSetAttribute(tgemm<2, true,  true>,  cudaFuncAttributeMaxDynamicSharedMemorySize, DSMEM);
    cudaFuncSetAttribute(tgemm<3, false, false>, cudaFuncAttributeMaxDynamicSharedMemorySize, DSMEM);
    cudaFuncSetAttribute(tgemm<4, false, true>,  cudaFuncAttributeMaxDynamicSharedMemorySize, DSMEM);
    cudaFuncSetAttribute(tgemm<0, false, false>, cudaFuncAttributeMaxDynamicSharedMemorySize, DSMEM);

    const int MS = Bsz * Sq;            // 4096
    const long sQ  = (long)Sq * Dm;
    const long sSS = (long)Sq * Sq;

    round_copy<<<(Bsz * Sq * Dm) / 1024, 256>>>(x, xr);
    fold_transpose<<<dim3(Dm / 32, Dm / 32), dim3(32, 8)>>>(ok, weffT);
    transpose_b<<<dim3(Dm / 32, Dm / 32, 1), dim3(32, 8)>>>(wi, wiT, Dm, Dm, 0, 0);

    // q = x @ wi (rounded output)
    tgemm<0, false, true><<<dim3(Dm / TILE, MS / TILE, 1), 256, DSMEM>>>(
        xr, wiT, q, MS, Dm, Dm, 0, 0, 0, 0.f, nullptr, nullptr, 0);

    transpose_b<<<dim3(Dm / 32, Sq / 32, Bsz), dim3(32, 8)>>>(q, qT, Sq, Dm, sQ, sQ);

    // scores = (q @ q^T)/32 causal
    tgemm<1, false, false><<<dim3(Sq / TILE, Sq / TILE, Bsz), 256, DSMEM>>>(
        q, q, sc, Sq, Sq, Dm, sQ, sQ, sSS, 1.f / 32.f, nullptr, nullptr, 0);

    softmax_rows<<<Bsz * Sq, 256>>>(sc);

    // head = P @ q + q
    tgemm<2, true, true><<<dim3(Dm / TILE, Sq / TILE, Bsz), 256, DSMEM>>>(
        sc, qT, head, Sq, Dm, Sq, sSS, sQ, sQ, 0.f, nullptr, q, sQ);

    // h = head @ Weff + bias
    tgemm<3, false, false><<<dim3(Dm / TILE, MS / TILE, 1), 256, DSMEM>>>(
        head, weffT, h, MS, Dm, Dm, 0, 0, 0, 0.f, ob, nullptr, 0);

    layernorm_rows<<<Bsz * Sq, 256>>>(h);

    // act = swish(h @ wi)
    tgemm<4, false, true><<<dim3(Dm / TILE, MS / TILE, 1), 256, DSMEM>>>(
        h, wiT, head, MS, Dm, Dm, 0, 0, 0, 0.f, nullptr, nullptr, 0);

    // out = act @ wi
    tgemm<0, false, false><<<dim3(Dm / TILE, MS / TILE, 1), 256, DSMEM>>>(
        head, wiT, out, MS, Dm, Dm, 0, 0, 0, 0.f, nullptr, nullptr, 0);
}